// round 1
// baseline (speedup 1.0000x reference)
#include <cuda_runtime.h>
#include <cuda_bf16.h>

// DiffJPEG: per-8x8-block  D X D^T -> round(./Q)*Q -> D^T Y D
// Input/output: (32, 3, 512, 512) float32. One thread owns one 8x8 block.
//
// D (8-pt DCT-II matrix) and Q (JPEG luma table @ quality 50 == base table)
// are compile-time constants -> all 2048 FMAs/thread use immediate multipliers.

static constexpr int IMG_W    = 512;
static constexpr int IMG_H    = 512;
static constexpr int NCHAN    = 32 * 3;                  // flattened B*C
static constexpr int BLK_X    = IMG_W / 8;               // 64
static constexpr int BLK_Y    = IMG_H / 8;               // 64
static constexpr int NBLOCKS  = NCHAN * BLK_Y * BLK_X;   // 393216
static constexpr int TPB      = 128;

__global__ void __launch_bounds__(TPB) diffjpeg_kernel(
    const float* __restrict__ in, float* __restrict__ out)
{
    const int bid = blockIdx.x * TPB + threadIdx.x;
    const int bx  = bid & (BLK_X - 1);
    const int t2  = bid >> 6;
    const int by  = t2 & (BLK_Y - 1);
    const int ch  = t2 >> 6;

    const size_t base = ((size_t)ch * IMG_H + (size_t)by * 8) * IMG_W + (size_t)bx * 8;
    const float* p = in + base;

    // ---- compile-time DCT matrix (half-cosines) ----
    const float h1 = 0.49039264020161522f;
    const float h2 = 0.46193976625564337f;
    const float h3 = 0.41573480615127262f;
    const float h4 = 0.35355339059327373f;
    const float h5 = 0.27778511650980114f;
    const float h6 = 0.19134171618254492f;
    const float h7 = 0.097545161008064166f;
    const float a0 = 0.35355339059327373f;  // sqrt(1/8)

    const float D[8][8] = {
        { a0,  a0,  a0,  a0,  a0,  a0,  a0,  a0},
        { h1,  h3,  h5,  h7, -h7, -h5, -h3, -h1},
        { h2,  h6, -h6, -h2, -h2, -h6,  h6,  h2},
        { h3, -h7, -h1, -h5,  h5,  h1,  h7, -h3},
        { h4, -h4, -h4,  h4,  h4, -h4, -h4,  h4},
        { h5, -h1,  h7,  h3, -h3, -h7,  h1, -h5},
        { h6, -h2,  h2, -h6, -h6,  h2, -h2,  h6},
        { h7, -h5,  h3, -h1,  h1, -h3,  h5, -h7},
    };

    // JPEG luma table; at quality=50 the scaled table equals the base table.
    const float Q[8][8] = {
        {16, 11, 10, 16, 24, 40, 51, 61},
        {12, 12, 14, 19, 26, 58, 60, 55},
        {14, 13, 16, 24, 40, 57, 69, 56},
        {14, 17, 22, 29, 51, 87, 80, 62},
        {18, 22, 37, 56, 68, 109, 103, 77},
        {24, 35, 55, 64, 81, 104, 113, 92},
        {49, 64, 78, 87, 103, 121, 120, 101},
        {72, 92, 95, 98, 112, 100, 103, 99},
    };
    const float QI[8][8] = {
        {1.0f/16, 1.0f/11, 1.0f/10, 1.0f/16, 1.0f/24, 1.0f/40, 1.0f/51, 1.0f/61},
        {1.0f/12, 1.0f/12, 1.0f/14, 1.0f/19, 1.0f/26, 1.0f/58, 1.0f/60, 1.0f/55},
        {1.0f/14, 1.0f/13, 1.0f/16, 1.0f/24, 1.0f/40, 1.0f/57, 1.0f/69, 1.0f/56},
        {1.0f/14, 1.0f/17, 1.0f/22, 1.0f/29, 1.0f/51, 1.0f/87, 1.0f/80, 1.0f/62},
        {1.0f/18, 1.0f/22, 1.0f/37, 1.0f/56, 1.0f/68, 1.0f/109, 1.0f/103, 1.0f/77},
        {1.0f/24, 1.0f/35, 1.0f/55, 1.0f/64, 1.0f/81, 1.0f/104, 1.0f/113, 1.0f/92},
        {1.0f/49, 1.0f/64, 1.0f/78, 1.0f/87, 1.0f/103, 1.0f/121, 1.0f/120, 1.0f/101},
        {1.0f/72, 1.0f/92, 1.0f/95, 1.0f/98, 1.0f/112, 1.0f/100, 1.0f/103, 1.0f/99},
    };

    // ---- load 8x8 block (2x float4 per row, coalesced across the warp) ----
    float x[8][8];
#pragma unroll
    for (int r = 0; r < 8; ++r) {
        const float4 va = *reinterpret_cast<const float4*>(p + (size_t)r * IMG_W);
        const float4 vb = *reinterpret_cast<const float4*>(p + (size_t)r * IMG_W + 4);
        x[r][0] = va.x; x[r][1] = va.y; x[r][2] = va.z; x[r][3] = va.w;
        x[r][4] = vb.x; x[r][5] = vb.y; x[r][6] = vb.z; x[r][7] = vb.w;
    }

    float t[8][8];

    // ---- t = D @ x ----
#pragma unroll
    for (int i = 0; i < 8; ++i)
#pragma unroll
        for (int j = 0; j < 8; ++j) {
            float s = D[i][0] * x[0][j];
#pragma unroll
            for (int k = 1; k < 8; ++k) s = fmaf(D[i][k], x[k][j], s);
            t[i][j] = s;
        }

    // ---- y = t @ D^T, quantize + dequantize (round half-to-even) ----
#pragma unroll
    for (int i = 0; i < 8; ++i)
#pragma unroll
        for (int j = 0; j < 8; ++j) {
            float s = D[j][0] * t[i][0];
#pragma unroll
            for (int k = 1; k < 8; ++k) s = fmaf(D[j][k], t[i][k], s);
            x[i][j] = rintf(s * QI[i][j]) * Q[i][j];
        }

    // ---- u = D^T @ x ----
#pragma unroll
    for (int i = 0; i < 8; ++i)
#pragma unroll
        for (int j = 0; j < 8; ++j) {
            float s = D[0][i] * x[0][j];
#pragma unroll
            for (int k = 1; k < 8; ++k) s = fmaf(D[k][i], x[k][j], s);
            t[i][j] = s;
        }

    // ---- z = u @ D, store ----
    float* q = out + base;
#pragma unroll
    for (int i = 0; i < 8; ++i) {
        float z[8];
#pragma unroll
        for (int j = 0; j < 8; ++j) {
            float s = t[i][0] * D[0][j];
#pragma unroll
            for (int k = 1; k < 8; ++k) s = fmaf(t[i][k], D[k][j], s);
            z[j] = s;
        }
        float4 va, vb;
        va.x = z[0]; va.y = z[1]; va.z = z[2]; va.w = z[3];
        vb.x = z[4]; vb.y = z[5]; vb.z = z[6]; vb.w = z[7];
        *reinterpret_cast<float4*>(q + (size_t)i * IMG_W)     = va;
        *reinterpret_cast<float4*>(q + (size_t)i * IMG_W + 4) = vb;
    }
}

extern "C" void kernel_launch(void* const* d_in, const int* in_sizes, int n_in,
                              void* d_out, int out_size)
{
    const float* img = (const float*)d_in[0];
    float* out = (float*)d_out;
    diffjpeg_kernel<<<NBLOCKS / TPB, TPB>>>(img, out);
}

// round 2
// speedup vs baseline: 1.0555x; 1.0555x over previous
#include <cuda_runtime.h>
#include <cuda_bf16.h>

// DiffJPEG: per-8x8-block  D X D^T -> round(./Q)*Q -> D^T Y D
// Input/output: (32, 3, 512, 512) float32. One thread owns one 8x8 block.
//
// This version uses the even/odd butterfly factorization of the 8-pt DCT-II:
// 36 fma-pipe ops per 1D transform instead of 64 FFMA (1.67x fewer compute
// ops overall), and runs fully in place on a single 64-float register array.

static constexpr int IMG_W    = 512;
static constexpr int IMG_H    = 512;
static constexpr int NCHAN    = 32 * 3;                  // flattened B*C
static constexpr int BLK_X    = IMG_W / 8;               // 64
static constexpr int BLK_Y    = IMG_H / 8;               // 64
static constexpr int NBLOCKS  = NCHAN * BLK_Y * BLK_X;   // 393216
static constexpr int TPB      = 128;

// half-cosine constants: Hk = 0.5*cos(k*pi/16); A0 = sqrt(1/8) = H4
#define H1 0.49039264020161522f
#define H2 0.46193976625564337f
#define H3 0.41573480615127262f
#define H5 0.27778511650980114f
#define H6 0.19134171618254492f
#define H7 0.097545161008064166f
#define A0 0.35355339059327373f

// Forward 8-pt DCT-II, in place over v[0..7].
__device__ __forceinline__ void dct8(float v[8])
{
    const float s0 = v[0] + v[7], s1 = v[1] + v[6];
    const float s2 = v[2] + v[5], s3 = v[3] + v[4];
    const float d0 = v[0] - v[7], d1 = v[1] - v[6];
    const float d2 = v[2] - v[5], d3 = v[3] - v[4];

    const float e0 = s0 + s3, e1 = s1 + s2;
    const float f0 = s0 - s3, f1 = s1 - s2;

    v[0] = A0 * (e0 + e1);
    v[4] = A0 * (e0 - e1);
    v[2] = fmaf(H2, f0,  H6 * f1);
    v[6] = fmaf(H6, f0, -H2 * f1);

    v[1] = fmaf(H1, d0, fmaf( H3, d1, fmaf( H5, d2,  H7 * d3)));
    v[3] = fmaf(H3, d0, fmaf(-H7, d1, fmaf(-H1, d2, -H5 * d3)));
    v[5] = fmaf(H5, d0, fmaf(-H1, d1, fmaf( H7, d2,  H3 * d3)));
    v[7] = fmaf(H7, d0, fmaf(-H5, d1, fmaf( H3, d2, -H1 * d3)));
}

// Inverse (DCT-III = D^T), in place over v[0..7].
__device__ __forceinline__ void idct8(float v[8])
{
    const float p = A0 * (v[0] + v[4]);
    const float q = A0 * (v[0] - v[4]);
    const float r = fmaf(H2, v[2],  H6 * v[6]);
    const float s = fmaf(H6, v[2], -H2 * v[6]);

    const float E0 = p + r, E1 = q + s, E2 = q - s, E3 = p - r;

    const float O0 = fmaf(H1, v[1], fmaf( H3, v[3], fmaf( H5, v[5],  H7 * v[7])));
    const float O1 = fmaf(H3, v[1], fmaf(-H7, v[3], fmaf(-H1, v[5], -H5 * v[7])));
    const float O2 = fmaf(H5, v[1], fmaf(-H1, v[3], fmaf( H7, v[5],  H3 * v[7])));
    const float O3 = fmaf(H7, v[1], fmaf(-H5, v[3], fmaf( H3, v[5], -H1 * v[7])));

    v[0] = E0 + O0;  v[7] = E0 - O0;
    v[1] = E1 + O1;  v[6] = E1 - O1;
    v[2] = E2 + O2;  v[5] = E2 - O2;
    v[3] = E3 + O3;  v[4] = E3 - O3;
}

__global__ void __launch_bounds__(TPB) diffjpeg_kernel(
    const float* __restrict__ in, float* __restrict__ out)
{
    const int bid = blockIdx.x * TPB + threadIdx.x;
    const int bx  = bid & (BLK_X - 1);
    const int t2  = bid >> 6;
    const int by  = t2 & (BLK_Y - 1);
    const int ch  = t2 >> 6;

    const size_t base = ((size_t)ch * IMG_H + (size_t)by * 8) * IMG_W + (size_t)bx * 8;
    const float* p = in + base;

    // JPEG luma table @ quality 50 (== base table) and reciprocals.
    const float Q[8][8] = {
        {16, 11, 10, 16, 24, 40, 51, 61},
        {12, 12, 14, 19, 26, 58, 60, 55},
        {14, 13, 16, 24, 40, 57, 69, 56},
        {14, 17, 22, 29, 51, 87, 80, 62},
        {18, 22, 37, 56, 68, 109, 103, 77},
        {24, 35, 55, 64, 81, 104, 113, 92},
        {49, 64, 78, 87, 103, 121, 120, 101},
        {72, 92, 95, 98, 112, 100, 103, 99},
    };
    const float QI[8][8] = {
        {1.0f/16, 1.0f/11, 1.0f/10, 1.0f/16, 1.0f/24, 1.0f/40, 1.0f/51, 1.0f/61},
        {1.0f/12, 1.0f/12, 1.0f/14, 1.0f/19, 1.0f/26, 1.0f/58, 1.0f/60, 1.0f/55},
        {1.0f/14, 1.0f/13, 1.0f/16, 1.0f/24, 1.0f/40, 1.0f/57, 1.0f/69, 1.0f/56},
        {1.0f/14, 1.0f/17, 1.0f/22, 1.0f/29, 1.0f/51, 1.0f/87, 1.0f/80, 1.0f/62},
        {1.0f/18, 1.0f/22, 1.0f/37, 1.0f/56, 1.0f/68, 1.0f/109, 1.0f/103, 1.0f/77},
        {1.0f/24, 1.0f/35, 1.0f/55, 1.0f/64, 1.0f/81, 1.0f/104, 1.0f/113, 1.0f/92},
        {1.0f/49, 1.0f/64, 1.0f/78, 1.0f/87, 1.0f/103, 1.0f/121, 1.0f/120, 1.0f/101},
        {1.0f/72, 1.0f/92, 1.0f/95, 1.0f/98, 1.0f/112, 1.0f/100, 1.0f/103, 1.0f/99},
    };

    // ---- load 8x8 block (2x float4 per row, coalesced across the warp) ----
    float x[8][8];
#pragma unroll
    for (int r = 0; r < 8; ++r) {
        const float4 va = *reinterpret_cast<const float4*>(p + (size_t)r * IMG_W);
        const float4 vb = *reinterpret_cast<const float4*>(p + (size_t)r * IMG_W + 4);
        x[r][0] = va.x; x[r][1] = va.y; x[r][2] = va.z; x[r][3] = va.w;
        x[r][4] = vb.x; x[r][5] = vb.y; x[r][6] = vb.z; x[r][7] = vb.w;
    }

    // ---- forward 2D DCT: columns then rows (in place) ----
#pragma unroll
    for (int j = 0; j < 8; ++j) {
        float c[8];
#pragma unroll
        for (int i = 0; i < 8; ++i) c[i] = x[i][j];
        dct8(c);
#pragma unroll
        for (int i = 0; i < 8; ++i) x[i][j] = c[i];
    }
#pragma unroll
    for (int i = 0; i < 8; ++i) dct8(x[i]);

    // ---- quantize + dequantize (round half-to-even, matches jnp.round) ----
#pragma unroll
    for (int i = 0; i < 8; ++i)
#pragma unroll
        for (int j = 0; j < 8; ++j)
            x[i][j] = rintf(x[i][j] * QI[i][j]) * Q[i][j];

    // ---- inverse 2D DCT: columns then rows (in place) ----
#pragma unroll
    for (int j = 0; j < 8; ++j) {
        float c[8];
#pragma unroll
        for (int i = 0; i < 8; ++i) c[i] = x[i][j];
        idct8(c);
#pragma unroll
        for (int i = 0; i < 8; ++i) x[i][j] = c[i];
    }

    float* q = out + base;
#pragma unroll
    for (int i = 0; i < 8; ++i) {
        idct8(x[i]);
        float4 va, vb;
        va.x = x[i][0]; va.y = x[i][1]; va.z = x[i][2]; va.w = x[i][3];
        vb.x = x[i][4]; vb.y = x[i][5]; vb.z = x[i][6]; vb.w = x[i][7];
        *reinterpret_cast<float4*>(q + (size_t)i * IMG_W)     = va;
        *reinterpret_cast<float4*>(q + (size_t)i * IMG_W + 4) = vb;
    }
}

extern "C" void kernel_launch(void* const* d_in, const int* in_sizes, int n_in,
                              void* d_out, int out_size)
{
    const float* img = (const float*)d_in[0];
    float* out = (float*)d_out;
    diffjpeg_kernel<<<NBLOCKS / TPB, TPB>>>(img, out);
}